// round 5
// baseline (speedup 1.0000x reference)
#include <cuda_runtime.h>
#include <cuda_fp16.h>
#include <cstdint>

// LinearAttend: q,k,v [4][8][64][8192] f32 -> out same shape.
//   ks = softmax(k, axis=s); qs = softmax(q, axis=d) * D^-0.5
//   ctx = ks @ v^T (64x64/head); out = ctx^T @ qs
// fp16 m16n8k16 MMA (fp32 accum), ldmatrix feed, ex2.approx.f16x2 exps,
// Zk via ones-column MMA, pre-normalized half context, occupancy-first
// (no register staging): 256-thread CTAs, ~55 regs.

#define SQ 8192
#define DH 64
#define NHEADS 32
#define CHUNKS 16
#define CHUNK_S (SQ / CHUNKS)    // 512 -> 8 tiles of 64
#define LOG2E 1.4426950408889634f

__device__ float  g_ctx[NHEADS * DH * DH];   // fp32 accumulation scratch
__device__ float  g_zk[NHEADS * DH];         // sum_s exp(k[i,s])
__device__ __half g_ctxh[NHEADS * DH * DH];  // normalized half context

__device__ __forceinline__ uint32_t smem_u32(const void* p) {
    return (uint32_t)__cvta_generic_to_shared(p);
}
__device__ __forceinline__ void ldsm_x4(uint32_t* r, uint32_t a) {
    asm volatile("ldmatrix.sync.aligned.m8n8.x4.shared.b16 {%0,%1,%2,%3}, [%4];"
                 : "=r"(r[0]), "=r"(r[1]), "=r"(r[2]), "=r"(r[3]) : "r"(a));
}
__device__ __forceinline__ void ldsm_x2(uint32_t* r, uint32_t a) {
    asm volatile("ldmatrix.sync.aligned.m8n8.x2.shared.b16 {%0,%1}, [%2];"
                 : "=r"(r[0]), "=r"(r[1]) : "r"(a));
}
__device__ __forceinline__ void ldsm_x4t(uint32_t* r, uint32_t a) {
    asm volatile("ldmatrix.sync.aligned.m8n8.x4.trans.shared.b16 {%0,%1,%2,%3}, [%4];"
                 : "=r"(r[0]), "=r"(r[1]), "=r"(r[2]), "=r"(r[3]) : "r"(a));
}
__device__ __forceinline__ void mma_f16(float* d, const uint32_t* a, const uint32_t* b) {
    asm volatile(
        "mma.sync.aligned.m16n8k16.row.col.f32.f16.f16.f32 "
        "{%0,%1,%2,%3}, {%4,%5,%6,%7}, {%8,%9}, {%0,%1,%2,%3};"
        : "+f"(d[0]), "+f"(d[1]), "+f"(d[2]), "+f"(d[3])
        : "r"(a[0]), "r"(a[1]), "r"(a[2]), "r"(a[3]), "r"(b[0]), "r"(b[1]));
}
__device__ __forceinline__ uint32_t pack_h2(float hi, float lo) {
    uint32_t h;
    asm("cvt.rn.f16x2.f32 %0, %1, %2;" : "=r"(h) : "f"(hi), "f"(lo));
    return h;
}
__device__ __forceinline__ uint32_t ex2_h2(uint32_t y) {
    uint32_t r;
    asm("ex2.approx.f16x2 %0, %1;" : "=r"(r) : "r"(y));
    return r;
}

// ---------------------------------------------------------------------------
// Kernel 1: ctx[i][j] += sum_s exp(k[i,s]) * v[j,s]; Zk via ones-column MMA.
// grid (CHUNKS, NHEADS), block 256 (8 warps: warp = (i-block 16) x (j-half 32)).
// ---------------------------------------------------------------------------
__global__ __launch_bounds__(256) void ctx_kernel(const float* __restrict__ k,
                                                  const float* __restrict__ v) {
    __shared__ __half sA[64][72];   // exp(k) half [i][s]
    __shared__ __half sB[72][72];   // v half      [j][s]; rows 64..71 ones/zeros

    const int head = blockIdx.y;
    const int s0   = blockIdx.x * CHUNK_S;
    const int tid  = threadIdx.x;
    const int warp = tid >> 5;
    const int lane = tid & 31;
    const int wi   = warp & 3;      // i-block (16 rows)
    const int wn   = warp >> 2;     // j-half (32 cols)

    const float* kg = k + (size_t)head * DH * SQ;
    const float* vg = v + (size_t)head * DH * SQ;

    // rows 64..71 of B: row 64 = 1.0h (Zk column), rows 65..71 = 0
    for (int e = tid; e < 8 * 36; e += 256) {
        const int row = 64 + e / 36;
        *reinterpret_cast<uint32_t*>(&sB[row][(e % 36) * 2]) =
            (row == 64) ? 0x3C003C00u : 0u;
    }

    float acc[4][4];
#pragma unroll
    for (int n = 0; n < 4; ++n)
#pragma unroll
        for (int c = 0; c < 4; ++c) acc[n][c] = 0.0f;
    float accz[4] = {0.f, 0.f, 0.f, 0.f};

    const int r  = tid >> 4;         // 0..15
    const int c4 = (tid & 15) * 4;   // 0..60

    for (int t = 0; t < CHUNK_S / 64; ++t) {
        const int scol = s0 + t * 64 + c4;
#pragma unroll
        for (int ib = 0; ib < 4; ++ib) {
            const int row = ib * 16 + r;
            const size_t off = (size_t)row * SQ + scol;
            float4 kv = *reinterpret_cast<const float4*>(kg + off);
            float4 vv = *reinterpret_cast<const float4*>(vg + off);
            uint2 ek;
            ek.x = ex2_h2(pack_h2(kv.y * LOG2E, kv.x * LOG2E));
            ek.y = ex2_h2(pack_h2(kv.w * LOG2E, kv.z * LOG2E));
            *reinterpret_cast<uint2*>(&sA[row][c4]) = ek;
            uint2 vh;
            vh.x = pack_h2(vv.y, vv.x);
            vh.y = pack_h2(vv.w, vv.z);
            *reinterpret_cast<uint2*>(&sB[row][c4]) = vh;
        }
        __syncthreads();

#pragma unroll
        for (int kk = 0; kk < 4; ++kk) {
            uint32_t a[4];
            ldsm_x4(a, smem_u32(&sA[wi * 16 + (lane & 15)]
                                  [kk * 16 + (lane >> 4) * 8]));
#pragma unroll
            for (int np = 0; np < 2; ++np) {
                uint32_t b[4];
                ldsm_x4(b, smem_u32(&sB[wn * 32 + (np * 2 + (lane >> 4)) * 8 + (lane & 7)]
                                      [kk * 16 + ((lane >> 3) & 1) * 8]));
                mma_f16(acc[np * 2],     a, b);
                mma_f16(acc[np * 2 + 1], a, b + 2);
            }
            if (wn == 1) {
                uint32_t b2[2];
                ldsm_x2(b2, smem_u32(&sB[64 + (lane & 7)]
                                       [kk * 16 + ((lane >> 3) & 1) * 8]));
                mma_f16(accz, a, b2);
            }
        }
        __syncthreads();
    }

    float* ctx = g_ctx + head * DH * DH;
    const int i0 = wi * 16 + (lane >> 2);
    const int jb = wn * 32 + (lane & 3) * 2;
#pragma unroll
    for (int n = 0; n < 4; ++n) {
        const int j = jb + n * 8;
        atomicAdd(&ctx[i0 * 64 + j],           acc[n][0]);
        atomicAdd(&ctx[i0 * 64 + j + 1],       acc[n][1]);
        atomicAdd(&ctx[(i0 + 8) * 64 + j],     acc[n][2]);
        atomicAdd(&ctx[(i0 + 8) * 64 + j + 1], acc[n][3]);
    }
    if (wn == 1 && (lane & 3) == 0) {          // B col 64 = Zk
        atomicAdd(&g_zk[head * 64 + i0],     accz[0]);
        atomicAdd(&g_zk[head * 64 + i0 + 8], accz[2]);
    }
}

// ---------------------------------------------------------------------------
// Kernel 1.5: ctxh[i][j] = ctx[i][j] * 0.125 / Zk[i]   (half output)
// grid 32, block 128.
// ---------------------------------------------------------------------------
__global__ __launch_bounds__(128) void norm_kernel() {
    const int head = blockIdx.x;
    const int tid  = threadIdx.x;
    const float* ctx = g_ctx + head * DH * DH;
    __half* och = g_ctxh + head * DH * DH;

    const int base = tid * 32;
    const float inv = __fdividef(0.125f, g_zk[head * 64 + (base >> 6)]);
#pragma unroll
    for (int p = 0; p < 4; ++p) {
        float4 a = *reinterpret_cast<const float4*>(ctx + base + p * 8);
        float4 b = *reinterpret_cast<const float4*>(ctx + base + p * 8 + 4);
        uint4 o;
        o.x = pack_h2(a.y * inv, a.x * inv);
        o.y = pack_h2(a.w * inv, a.z * inv);
        o.z = pack_h2(b.y * inv, b.x * inv);
        o.w = pack_h2(b.w * inv, b.z * inv);
        *reinterpret_cast<uint4*>(och + base + p * 8) = o;
    }
}

// ---------------------------------------------------------------------------
// Kernel 2: out[j,s] = (1/Zq_s) * sum_i ctxh[i][j] * exp(q[i,s])
// grid (SQ/128, NHEADS), block 256. Tile 64 j x 128 s.
// ---------------------------------------------------------------------------
__global__ __launch_bounds__(256) void out_kernel(const float* __restrict__ q,
                                                  float* __restrict__ out) {
    __shared__ __half sCt[64][72];    // [i][j] normalized half context
    __shared__ __half sQ[64][136];    // [i][s] exp(q) half
    __shared__ float  sZp[8][132];    // Zq partials
    __shared__ float  sCs[128];       // 1/Zq_s

    const int head = blockIdx.y;
    const int s0   = blockIdx.x * 128;
    const int tid  = threadIdx.x;
    const int warp = tid >> 5;
    const int lane = tid & 31;

    const float* qg = q + (size_t)head * DH * SQ + s0;
    const int r  = tid >> 5;          // 0..7
    const int c4 = (tid & 31) * 4;    // 0..124

    // context tile: 256 threads x 2 uint4 = 8 KB
    {
        const uint4* src = reinterpret_cast<const uint4*>(g_ctxh + head * DH * DH);
        uint4 c0 = src[tid * 2];
        uint4 c1 = src[tid * 2 + 1];
        const int i = tid >> 2;
        const int j = (tid & 3) * 16;
        *reinterpret_cast<uint4*>(&sCt[i][j])     = c0;
        *reinterpret_cast<uint4*>(&sCt[i][j + 8]) = c1;
    }

    // exp(q) via ex2.f16x2; Zq partials accumulated in f32 from the halves
    float4 zp = make_float4(0.f, 0.f, 0.f, 0.f);
#pragma unroll
    for (int ib = 0; ib < 8; ++ib) {
        const int d = ib * 8 + r;
        float4 qv = *reinterpret_cast<const float4*>(qg + (size_t)d * SQ + c4);
        uint2 eq;
        eq.x = ex2_h2(pack_h2(qv.y * LOG2E, qv.x * LOG2E));
        eq.y = ex2_h2(pack_h2(qv.w * LOG2E, qv.z * LOG2E));
        *reinterpret_cast<uint2*>(&sQ[d][c4]) = eq;
        float2 e0 = __half22float2(*reinterpret_cast<__half2*>(&eq.x));
        float2 e1 = __half22float2(*reinterpret_cast<__half2*>(&eq.y));
        zp.x += e0.x; zp.y += e0.y; zp.z += e1.x; zp.w += e1.y;
    }
    *reinterpret_cast<float4*>(&sZp[r][c4]) = zp;
    __syncthreads();

    if (tid < 128) {
        float z = 0.0f;
#pragma unroll
        for (int d = 0; d < 8; ++d) z += sZp[d][tid];
        sCs[tid] = __fdividef(1.0f, z);
    }

    float acc[8][4];
#pragma unroll
    for (int n = 0; n < 8; ++n)
#pragma unroll
        for (int c = 0; c < 4; ++c) acc[n][c] = 0.0f;

    const int jw = (warp & 3) * 16;   // j offset
    const int sw = (warp >> 2) * 64;  // s offset

#pragma unroll
    for (int kk = 0; kk < 4; ++kk) {
        uint32_t a[4];
        ldsm_x4t(a, smem_u32(&sCt[kk * 16 + (lane & 7) + (lane >> 4) * 8]
                                [jw + ((lane >> 3) & 1) * 8]));
#pragma unroll
        for (int np = 0; np < 4; ++np) {
            uint32_t b[4];
            ldsm_x4t(b, smem_u32(&sQ[kk * 16 + (lane & 7) + ((lane >> 3) & 1) * 8]
                                    [sw + (np * 2 + (lane >> 4)) * 8]));
            mma_f16(acc[np * 2],     a, b);
            mma_f16(acc[np * 2 + 1], a, b + 2);
        }
    }
    __syncthreads();   // sCs ready (reduce overlapped with MMA issue)

    float* og = out + (size_t)head * DH * SQ + s0;
    const int j0 = jw + (lane >> 2);
    const int sc = (lane & 3) * 2;
#pragma unroll
    for (int n = 0; n < 8; ++n) {
        const int s = sw + n * 8 + sc;
        const float inv0 = sCs[s];
        const float inv1 = sCs[s + 1];
        float2 w0 = make_float2(acc[n][0] * inv0, acc[n][1] * inv1);
        float2 w1 = make_float2(acc[n][2] * inv0, acc[n][3] * inv1);
        *reinterpret_cast<float2*>(og + (size_t)j0 * SQ + s) = w0;
        *reinterpret_cast<float2*>(og + (size_t)(j0 + 8) * SQ + s) = w1;
    }
}

// ---------------------------------------------------------------------------
extern "C" void kernel_launch(void* const* d_in, const int* in_sizes, int n_in,
                              void* d_out, int out_size) {
    const float* q = (const float*)d_in[0];
    const float* k = (const float*)d_in[1];
    const float* v = (const float*)d_in[2];
    float* out = (float*)d_out;

    void* ctx_ptr = nullptr;
    void* zk_ptr  = nullptr;
    cudaGetSymbolAddress(&ctx_ptr, g_ctx);
    cudaGetSymbolAddress(&zk_ptr, g_zk);
    cudaMemsetAsync(ctx_ptr, 0, NHEADS * DH * DH * sizeof(float));
    cudaMemsetAsync(zk_ptr, 0, NHEADS * DH * sizeof(float));

    ctx_kernel<<<dim3(CHUNKS, NHEADS), 256>>>(k, v);
    norm_kernel<<<NHEADS, 128>>>();
    out_kernel<<<dim3(SQ / 128, NHEADS), 256>>>(q, out);
}

// round 6
// speedup vs baseline: 1.0243x; 1.0243x over previous
#include <cuda_runtime.h>
#include <cuda_fp16.h>
#include <cstdint>

// LinearAttend: q,k,v [4][8][64][8192] f32 -> out same shape.
//   ks = softmax(k, axis=s); qs = softmax(q, axis=d) * D^-0.5
//   ctx = ks @ v^T (64x64/head); out = ctx^T @ qs
// fp16 m16n8k16 MMA (fp32 accum), ldmatrix feed, ex2.approx.f16x2 exps,
// Zk via ones-column MMA, pre-normalized half context.
// This round: cp.async double-buffered f32 staging so DRAM streams through
// the compute phases; persistent multi-tile CTAs in both GEMM kernels.

#define SQ 8192
#define DH 64
#define NHEADS 32
#define CHUNKS 8
#define CHUNK_S (SQ / CHUNKS)     // 1024 -> 16 tiles of 64
#define OUT_TPC 8                 // s-tiles (128 wide) per out CTA
#define LOG2E 1.4426950408889634f

__device__ float  g_ctx[NHEADS * DH * DH];
__device__ float  g_zk[NHEADS * DH];
__device__ __half g_ctxh[NHEADS * DH * DH];

__device__ __forceinline__ uint32_t smem_u32(const void* p) {
    return (uint32_t)__cvta_generic_to_shared(p);
}
__device__ __forceinline__ void cp_async16(uint32_t dst, const void* src) {
    asm volatile("cp.async.cg.shared.global [%0], [%1], 16;" :: "r"(dst), "l"(src));
}
__device__ __forceinline__ void cp_commit() {
    asm volatile("cp.async.commit_group;");
}
__device__ __forceinline__ void cp_wait1() {
    asm volatile("cp.async.wait_group 1;");
}
__device__ __forceinline__ void ldsm_x4(uint32_t* r, uint32_t a) {
    asm volatile("ldmatrix.sync.aligned.m8n8.x4.shared.b16 {%0,%1,%2,%3}, [%4];"
                 : "=r"(r[0]), "=r"(r[1]), "=r"(r[2]), "=r"(r[3]) : "r"(a));
}
__device__ __forceinline__ void ldsm_x2(uint32_t* r, uint32_t a) {
    asm volatile("ldmatrix.sync.aligned.m8n8.x2.shared.b16 {%0,%1}, [%2];"
                 : "=r"(r[0]), "=r"(r[1]) : "r"(a));
}
__device__ __forceinline__ void ldsm_x4t(uint32_t* r, uint32_t a) {
    asm volatile("ldmatrix.sync.aligned.m8n8.x4.trans.shared.b16 {%0,%1,%2,%3}, [%4];"
                 : "=r"(r[0]), "=r"(r[1]), "=r"(r[2]), "=r"(r[3]) : "r"(a));
}
__device__ __forceinline__ void mma_f16(float* d, const uint32_t* a, const uint32_t* b) {
    asm volatile(
        "mma.sync.aligned.m16n8k16.row.col.f32.f16.f16.f32 "
        "{%0,%1,%2,%3}, {%4,%5,%6,%7}, {%8,%9}, {%0,%1,%2,%3};"
        : "+f"(d[0]), "+f"(d[1]), "+f"(d[2]), "+f"(d[3])
        : "r"(a[0]), "r"(a[1]), "r"(a[2]), "r"(a[3]), "r"(b[0]), "r"(b[1]));
}
__device__ __forceinline__ uint32_t pack_h2(float hi, float lo) {
    uint32_t h;
    asm("cvt.rn.f16x2.f32 %0, %1, %2;" : "=r"(h) : "f"(hi), "f"(lo));
    return h;
}
__device__ __forceinline__ uint32_t ex2_h2(uint32_t y) {
    uint32_t r;
    asm("ex2.approx.f16x2 %0, %1;" : "=r"(r) : "r"(y));
    return r;
}

// ---------------------------------------------------------------------------
// Kernel 1: ctx[i][j] += sum_s exp(k[i,s]) * v[j,s]; Zk via ones-column MMA.
// grid (CHUNKS, NHEADS), block 256. cp.async double-buffered f32 staging.
// dyn smem: sKf[2][64][64] | sVf[2][64][64] | sA[64][72] | sB[72][72]
// ---------------------------------------------------------------------------
#define CTX_SA_OFF 65536
#define CTX_SB_OFF 74752
#define CTX_SMEM   85120

__global__ __launch_bounds__(256) void ctx_kernel(const float* __restrict__ k,
                                                  const float* __restrict__ v) {
    extern __shared__ char dyn[];
    float* sKf = reinterpret_cast<float*>(dyn);            // [2][64*64]
    float* sVf = reinterpret_cast<float*>(dyn + 32768);    // [2][64*64]
    __half (*sA)[72] = reinterpret_cast<__half(*)[72]>(dyn + CTX_SA_OFF);
    __half (*sB)[72] = reinterpret_cast<__half(*)[72]>(dyn + CTX_SB_OFF);

    const int head = blockIdx.y;
    const int s0   = blockIdx.x * CHUNK_S;
    const int tid  = threadIdx.x;
    const int warp = tid >> 5;
    const int lane = tid & 31;
    const int wi   = warp & 3;      // i-block (16 rows)
    const int wn   = warp >> 2;     // j-half (32 cols)

    const float* kg = k + (size_t)head * DH * SQ;
    const float* vg = v + (size_t)head * DH * SQ;

    // B rows 64..71: row 64 = 1.0h (Zk column), rows 65..71 = 0
    for (int e = tid; e < 8 * 36; e += 256) {
        const int row = 64 + e / 36;
        *reinterpret_cast<uint32_t*>(&sB[row][(e % 36) * 2]) =
            (row == 64) ? 0x3C003C00u : 0u;
    }

    const int r0  = tid >> 4;        // 0..15
    const int c4  = (tid & 15) * 4;  // float offset within 64-wide row

    // prologue: stage tiles 0 and 1
#pragma unroll
    for (int st = 0; st < 2; ++st) {
        const int scol = s0 + st * 64 + c4;
#pragma unroll
        for (int ib = 0; ib < 4; ++ib) {
            const int row = ib * 16 + r0;
            cp_async16(smem_u32(sKf + st * 4096 + row * 64 + c4), kg + (size_t)row * SQ + scol);
            cp_async16(smem_u32(sVf + st * 4096 + row * 64 + c4), vg + (size_t)row * SQ + scol);
        }
        cp_commit();
    }

    float acc[4][4];
#pragma unroll
    for (int n = 0; n < 4; ++n)
#pragma unroll
        for (int c = 0; c < 4; ++c) acc[n][c] = 0.0f;
    float accz[4] = {0.f, 0.f, 0.f, 0.f};

    const int NT = CHUNK_S / 64;     // 16
    for (int t = 0; t < NT; ++t) {
        const int st = t & 1;
        cp_wait1();
        __syncthreads();

        // convert staged f32 -> half tiles (exp for k)
        const float* kf = sKf + st * 4096;
        const float* vf = sVf + st * 4096;
#pragma unroll
        for (int ib = 0; ib < 4; ++ib) {
            const int row = ib * 16 + r0;
            float4 kv = *reinterpret_cast<const float4*>(kf + row * 64 + c4);
            float4 vv = *reinterpret_cast<const float4*>(vf + row * 64 + c4);
            uint2 ek;
            ek.x = ex2_h2(pack_h2(kv.y * LOG2E, kv.x * LOG2E));
            ek.y = ex2_h2(pack_h2(kv.w * LOG2E, kv.z * LOG2E));
            *reinterpret_cast<uint2*>(&sA[row][c4]) = ek;
            uint2 vh;
            vh.x = pack_h2(vv.y, vv.x);
            vh.y = pack_h2(vv.w, vv.z);
            *reinterpret_cast<uint2*>(&sB[row][c4]) = vh;
        }
        __syncthreads();

        // prefetch tile t+2 into the stage we just drained
        if (t + 2 < NT) {
            const int scol = s0 + (t + 2) * 64 + c4;
#pragma unroll
            for (int ib = 0; ib < 4; ++ib) {
                const int row = ib * 16 + r0;
                cp_async16(smem_u32(sKf + st * 4096 + row * 64 + c4), kg + (size_t)row * SQ + scol);
                cp_async16(smem_u32(sVf + st * 4096 + row * 64 + c4), vg + (size_t)row * SQ + scol);
            }
        }
        cp_commit();

        // MMA while the prefetch streams
#pragma unroll
        for (int kk = 0; kk < 4; ++kk) {
            uint32_t a[4];
            ldsm_x4(a, smem_u32(&sA[wi * 16 + (lane & 15)]
                                  [kk * 16 + (lane >> 4) * 8]));
#pragma unroll
            for (int np = 0; np < 2; ++np) {
                uint32_t b[4];
                ldsm_x4(b, smem_u32(&sB[wn * 32 + (np * 2 + (lane >> 4)) * 8 + (lane & 7)]
                                      [kk * 16 + ((lane >> 3) & 1) * 8]));
                mma_f16(acc[np * 2],     a, b);
                mma_f16(acc[np * 2 + 1], a, b + 2);
            }
            if (wn == 1) {
                uint32_t b2[2];
                ldsm_x2(b2, smem_u32(&sB[64 + (lane & 7)]
                                       [kk * 16 + ((lane >> 3) & 1) * 8]));
                mma_f16(accz, a, b2);
            }
        }
    }

    float* ctx = g_ctx + head * DH * DH;
    const int i0 = wi * 16 + (lane >> 2);
    const int jb = wn * 32 + (lane & 3) * 2;
#pragma unroll
    for (int n = 0; n < 4; ++n) {
        const int j = jb + n * 8;
        atomicAdd(&ctx[i0 * 64 + j],           acc[n][0]);
        atomicAdd(&ctx[i0 * 64 + j + 1],       acc[n][1]);
        atomicAdd(&ctx[(i0 + 8) * 64 + j],     acc[n][2]);
        atomicAdd(&ctx[(i0 + 8) * 64 + j + 1], acc[n][3]);
    }
    if (wn == 1 && (lane & 3) == 0) {
        atomicAdd(&g_zk[head * 64 + i0],     accz[0]);
        atomicAdd(&g_zk[head * 64 + i0 + 8], accz[2]);
    }
}

// ---------------------------------------------------------------------------
// Kernel 1.5: ctxh[i][j] = ctx[i][j] * 0.125 / Zk[i]
// ---------------------------------------------------------------------------
__global__ __launch_bounds__(128) void norm_kernel() {
    const int head = blockIdx.x;
    const int tid  = threadIdx.x;
    const float* ctx = g_ctx + head * DH * DH;
    __half* och = g_ctxh + head * DH * DH;

    const int base = tid * 32;
    const float inv = __fdividef(0.125f, g_zk[head * 64 + (base >> 6)]);
#pragma unroll
    for (int p = 0; p < 4; ++p) {
        float4 a = *reinterpret_cast<const float4*>(ctx + base + p * 8);
        float4 b = *reinterpret_cast<const float4*>(ctx + base + p * 8 + 4);
        uint4 o;
        o.x = pack_h2(a.y * inv, a.x * inv);
        o.y = pack_h2(a.w * inv, a.z * inv);
        o.z = pack_h2(b.y * inv, b.x * inv);
        o.w = pack_h2(b.w * inv, b.z * inv);
        *reinterpret_cast<uint4*>(och + base + p * 8) = o;
    }
}

// ---------------------------------------------------------------------------
// Kernel 2: out[j,s] = (1/Zq_s) * sum_i ctxh[i][j] * exp(q[i,s])
// grid (SQ/128/OUT_TPC, NHEADS), block 256. Persistent over OUT_TPC s-tiles,
// cp.async double-buffered q staging.
// dyn smem: sQf[2][64][128] | sQ[64][136] | sCt[64][72] | sZp[8][132] | sCs[128]
// ---------------------------------------------------------------------------
#define OUT_SQ_OFF  65536
#define OUT_SCT_OFF (OUT_SQ_OFF + 64 * 136 * 2)     // 82944
#define OUT_SZP_OFF (OUT_SCT_OFF + 64 * 72 * 2)     // 92160
#define OUT_SCS_OFF (OUT_SZP_OFF + 8 * 132 * 4)     // 96384
#define OUT_SMEM    (OUT_SCS_OFF + 128 * 4)         // 96896

__global__ __launch_bounds__(256) void out_kernel(const float* __restrict__ q,
                                                  float* __restrict__ out) {
    extern __shared__ char dyn[];
    float* sQf = reinterpret_cast<float*>(dyn);            // [2][64*128]
    __half (*sQ)[136] = reinterpret_cast<__half(*)[136]>(dyn + OUT_SQ_OFF);
    __half (*sCt)[72] = reinterpret_cast<__half(*)[72]>(dyn + OUT_SCT_OFF);
    float (*sZp)[132] = reinterpret_cast<float(*)[132]>(dyn + OUT_SZP_OFF);
    float* sCs = reinterpret_cast<float*>(dyn + OUT_SCS_OFF);

    const int head = blockIdx.y;
    const int tid  = threadIdx.x;
    const int warp = tid >> 5;
    const int lane = tid & 31;

    const float* qg = q + (size_t)head * DH * SQ;
    const int sbase = blockIdx.x * OUT_TPC * 128;

    const int r  = tid >> 5;          // 0..7
    const int c4 = (tid & 31) * 4;    // 0..124

    // prologue: stage q tiles 0 and 1
#pragma unroll
    for (int st = 0; st < 2; ++st) {
        const int scol = sbase + st * 128 + c4;
#pragma unroll
        for (int ib = 0; ib < 8; ++ib) {
            const int d = ib * 8 + r;
            cp_async16(smem_u32(sQf + st * 8192 + d * 128 + c4), qg + (size_t)d * SQ + scol);
        }
        cp_commit();
    }

    // context tile (LDG flies under the cp.async waits)
    {
        const uint4* src = reinterpret_cast<const uint4*>(g_ctxh + head * DH * DH);
        uint4 c0 = src[tid * 2];
        uint4 c1 = src[tid * 2 + 1];
        const int i = tid >> 2;
        const int j = (tid & 3) * 16;
        *reinterpret_cast<uint4*>(&sCt[i][j])     = c0;
        *reinterpret_cast<uint4*>(&sCt[i][j + 8]) = c1;
    }

    const int jw = (warp & 3) * 16;
    const int sw = (warp >> 2) * 64;

    for (int t = 0; t < OUT_TPC; ++t) {
        const int st = t & 1;
        cp_wait1();
        __syncthreads();

        // convert: exp(q) -> half, Zq partials in f32 from the halves
        const float* qf = sQf + st * 8192;
        float4 zp = make_float4(0.f, 0.f, 0.f, 0.f);
#pragma unroll
        for (int ib = 0; ib < 8; ++ib) {
            const int d = ib * 8 + r;
            float4 qv = *reinterpret_cast<const float4*>(qf + d * 128 + c4);
            uint2 eq;
            eq.x = ex2_h2(pack_h2(qv.y * LOG2E, qv.x * LOG2E));
            eq.y = ex2_h2(pack_h2(qv.w * LOG2E, qv.z * LOG2E));
            *reinterpret_cast<uint2*>(&sQ[d][c4]) = eq;
            float2 e0 = __half22float2(*reinterpret_cast<__half2*>(&eq.x));
            float2 e1 = __half22float2(*reinterpret_cast<__half2*>(&eq.y));
            zp.x += e0.x; zp.y += e0.y; zp.z += e1.x; zp.w += e1.y;
        }
        *reinterpret_cast<float4*>(&sZp[r][c4]) = zp;
        __syncthreads();

        // prefetch q tile t+2
        if (t + 2 < OUT_TPC) {
            const int scol = sbase + (t + 2) * 128 + c4;
#pragma unroll
            for (int ib = 0; ib < 8; ++ib) {
                const int d = ib * 8 + r;
                cp_async16(smem_u32(sQf + st * 8192 + d * 128 + c4), qg + (size_t)d * SQ + scol);
            }
        }
        cp_commit();

        if (tid < 128) {
            float z = 0.0f;
#pragma unroll
            for (int d = 0; d < 8; ++d) z += sZp[d][tid];
            sCs[tid] = __fdividef(1.0f, z);
        }

        float acc[8][4];
#pragma unroll
        for (int n = 0; n < 8; ++n)
#pragma unroll
            for (int c = 0; c < 4; ++c) acc[n][c] = 0.0f;

#pragma unroll
        for (int kk = 0; kk < 4; ++kk) {
            uint32_t a[4];
            ldsm_x4t(a, smem_u32(&sCt[kk * 16 + (lane & 7) + (lane >> 4) * 8]
                                    [jw + ((lane >> 3) & 1) * 8]));
#pragma unroll
            for (int np = 0; np < 4; ++np) {
                uint32_t b[4];
                ldsm_x4t(b, smem_u32(&sQ[kk * 16 + (lane & 7) + ((lane >> 3) & 1) * 8]
                                        [sw + (np * 2 + (lane >> 4)) * 8]));
                mma_f16(acc[np * 2],     a, b);
                mma_f16(acc[np * 2 + 1], a, b + 2);
            }
        }
        __syncthreads();   // sCs ready; also fences sQ/sZp for next iteration

        float* og = out + (size_t)head * DH * SQ + sbase + t * 128;
        const int j0 = jw + (lane >> 2);
        const int sc = (lane & 3) * 2;
#pragma unroll
        for (int n = 0; n < 8; ++n) {
            const int s = sw + n * 8 + sc;
            const float inv0 = sCs[s];
            const float inv1 = sCs[s + 1];
            float2 w0 = make_float2(acc[n][0] * inv0, acc[n][1] * inv1);
            float2 w1 = make_float2(acc[n][2] * inv0, acc[n][3] * inv1);
            *reinterpret_cast<float2*>(og + (size_t)j0 * SQ + s) = w0;
            *reinterpret_cast<float2*>(og + (size_t)(j0 + 8) * SQ + s) = w1;
        }
    }
}

// ---------------------------------------------------------------------------
extern "C" void kernel_launch(void* const* d_in, const int* in_sizes, int n_in,
                              void* d_out, int out_size) {
    const float* q = (const float*)d_in[0];
    const float* k = (const float*)d_in[1];
    const float* v = (const float*)d_in[2];
    float* out = (float*)d_out;

    cudaFuncSetAttribute(ctx_kernel, cudaFuncAttributeMaxDynamicSharedMemorySize, CTX_SMEM);
    cudaFuncSetAttribute(out_kernel, cudaFuncAttributeMaxDynamicSharedMemorySize, OUT_SMEM);

    void* ctx_ptr = nullptr;
    void* zk_ptr  = nullptr;
    cudaGetSymbolAddress(&ctx_ptr, g_ctx);
    cudaGetSymbolAddress(&zk_ptr, g_zk);
    cudaMemsetAsync(ctx_ptr, 0, NHEADS * DH * DH * sizeof(float));
    cudaMemsetAsync(zk_ptr, 0, NHEADS * DH * sizeof(float));

    ctx_kernel<<<dim3(CHUNKS, NHEADS), 256, CTX_SMEM>>>(k, v);
    norm_kernel<<<NHEADS, 128>>>();
    out_kernel<<<dim3(SQ / 128 / OUT_TPC, NHEADS), 256, OUT_SMEM>>>(q, out);
}

// round 7
// speedup vs baseline: 1.0560x; 1.0309x over previous
#include <cuda_runtime.h>
#include <cuda_fp16.h>
#include <cstdint>

// LinearAttend: q,k,v [4][8][64][8192] f32 -> out same shape.
//   ks = softmax(k, axis=s); qs = softmax(q, axis=d) * D^-0.5
//   ctx = ks @ v^T (64x64/head); out = ctx^T @ qs
// fp16 m16n8k16 MMA (fp32 accum), ldmatrix feed, ex2.approx.f16x2 exps,
// Zk via ones-column MMA. This round: one barrier per tile (per-thread
// self-consistent cp.async staging + double-buffered half tiles),
// atomic-free split-K via per-chunk partials summed in out's prologue,
// no memset / no norm kernel.

#define SQ 8192
#define DH 64
#define NHEADS 32
#define CHUNKS 8
#define CHUNK_S (SQ / CHUNKS)     // 1024 -> 16 tiles of 64
#define OUT_TPC 8                 // 128-wide s-tiles per out CTA
#define LOG2E 1.4426950408889634f

__device__ float g_ctx_part[CHUNKS * NHEADS * DH * DH];  // 4 MB partials
__device__ float g_zk_part[CHUNKS * NHEADS * DH];        // Zk partials

__device__ __forceinline__ uint32_t smem_u32(const void* p) {
    return (uint32_t)__cvta_generic_to_shared(p);
}
__device__ __forceinline__ void cp_async16(uint32_t dst, const void* src) {
    asm volatile("cp.async.cg.shared.global [%0], [%1], 16;" :: "r"(dst), "l"(src));
}
__device__ __forceinline__ void cp_commit() {
    asm volatile("cp.async.commit_group;");
}
__device__ __forceinline__ void cp_wait1() {
    asm volatile("cp.async.wait_group 1;");
}
__device__ __forceinline__ void ldsm_x4(uint32_t* r, uint32_t a) {
    asm volatile("ldmatrix.sync.aligned.m8n8.x4.shared.b16 {%0,%1,%2,%3}, [%4];"
                 : "=r"(r[0]), "=r"(r[1]), "=r"(r[2]), "=r"(r[3]) : "r"(a));
}
__device__ __forceinline__ void ldsm_x2(uint32_t* r, uint32_t a) {
    asm volatile("ldmatrix.sync.aligned.m8n8.x2.shared.b16 {%0,%1}, [%2];"
                 : "=r"(r[0]), "=r"(r[1]) : "r"(a));
}
__device__ __forceinline__ void ldsm_x4t(uint32_t* r, uint32_t a) {
    asm volatile("ldmatrix.sync.aligned.m8n8.x4.trans.shared.b16 {%0,%1,%2,%3}, [%4];"
                 : "=r"(r[0]), "=r"(r[1]), "=r"(r[2]), "=r"(r[3]) : "r"(a));
}
__device__ __forceinline__ void mma_f16(float* d, const uint32_t* a, const uint32_t* b) {
    asm volatile(
        "mma.sync.aligned.m16n8k16.row.col.f32.f16.f16.f32 "
        "{%0,%1,%2,%3}, {%4,%5,%6,%7}, {%8,%9}, {%0,%1,%2,%3};"
        : "+f"(d[0]), "+f"(d[1]), "+f"(d[2]), "+f"(d[3])
        : "r"(a[0]), "r"(a[1]), "r"(a[2]), "r"(a[3]), "r"(b[0]), "r"(b[1]));
}
__device__ __forceinline__ uint32_t pack_h2(float hi, float lo) {
    uint32_t h;
    asm("cvt.rn.f16x2.f32 %0, %1, %2;" : "=r"(h) : "f"(hi), "f"(lo));
    return h;
}
__device__ __forceinline__ uint32_t ex2_h2(uint32_t y) {
    uint32_t r;
    asm("ex2.approx.f16x2 %0, %1;" : "=r"(r) : "r"(y));
    return r;
}

// ---------------------------------------------------------------------------
// Kernel 1: ctx partials. grid (CHUNKS, NHEADS), block 256.
// dyn smem: sKf[2][4096]f | sVf[2][4096]f | sA[2][64][72]h | sB[2][72][72]h
// ---------------------------------------------------------------------------
#define CTX_SVF_OFF 32768
#define CTX_SA_OFF  65536
#define CTX_SB_OFF  83968
#define CTX_SMEM    104704

__global__ __launch_bounds__(256, 2) void ctx_kernel(const float* __restrict__ k,
                                                     const float* __restrict__ v) {
    extern __shared__ char dyn[];
    float* sKf = reinterpret_cast<float*>(dyn);
    float* sVf = reinterpret_cast<float*>(dyn + CTX_SVF_OFF);
    __half (*sAb)[72] = reinterpret_cast<__half(*)[72]>(dyn + CTX_SA_OFF);
    __half (*sBb)[72] = reinterpret_cast<__half(*)[72]>(dyn + CTX_SB_OFF);

    const int head = blockIdx.y;
    const int s0   = blockIdx.x * CHUNK_S;
    const int tid  = threadIdx.x;
    const int warp = tid >> 5;
    const int lane = tid & 31;
    const int wi   = warp & 3;      // i-block (16 rows)
    const int wn   = warp >> 2;     // j-half (32 cols)

    const float* kg = k + (size_t)head * DH * SQ;
    const float* vg = v + (size_t)head * DH * SQ;

    // both B buffers: row 64 = 1.0h (Zk column), rows 65..71 = 0
    for (int e = tid; e < 2 * 8 * 36; e += 256) {
        const int stg = e / (8 * 36);
        const int rem = e % (8 * 36);
        const int row = 64 + rem / 36;
        *reinterpret_cast<uint32_t*>(&sBb[stg * 72 + row][(rem % 36) * 2]) =
            (row == 64) ? 0x3C003C00u : 0u;
    }

    const int r0 = tid >> 4;         // 0..15
    const int c4 = (tid & 15) * 4;   // 0..60

    // prologue: stage tiles 0,1
#pragma unroll
    for (int st = 0; st < 2; ++st) {
        const int scol = s0 + st * 64 + c4;
#pragma unroll
        for (int ib = 0; ib < 4; ++ib) {
            const int row = ib * 16 + r0;
            cp_async16(smem_u32(sKf + st * 4096 + row * 64 + c4), kg + (size_t)row * SQ + scol);
            cp_async16(smem_u32(sVf + st * 4096 + row * 64 + c4), vg + (size_t)row * SQ + scol);
        }
        cp_commit();
    }

    float acc[4][4];
#pragma unroll
    for (int n = 0; n < 4; ++n)
#pragma unroll
        for (int c = 0; c < 4; ++c) acc[n][c] = 0.0f;
    float accz[4] = {0.f, 0.f, 0.f, 0.f};

    const int NT = CHUNK_S / 64;     // 16
    for (int t = 0; t < NT; ++t) {
        const int st = t & 1;
        __half (*sA)[72] = sAb + st * 64;
        __half (*sB)[72] = sBb + st * 72;

        cp_wait1();                  // per-thread: this thread's rows landed

        // convert (reads exactly what this thread staged -> no barrier needed)
        const float* kf = sKf + st * 4096;
        const float* vf = sVf + st * 4096;
#pragma unroll
        for (int ib = 0; ib < 4; ++ib) {
            const int row = ib * 16 + r0;
            float4 kv = *reinterpret_cast<const float4*>(kf + row * 64 + c4);
            float4 vv = *reinterpret_cast<const float4*>(vf + row * 64 + c4);
            uint2 ek;
            ek.x = ex2_h2(pack_h2(kv.y * LOG2E, kv.x * LOG2E));
            ek.y = ex2_h2(pack_h2(kv.w * LOG2E, kv.z * LOG2E));
            *reinterpret_cast<uint2*>(&sA[row][c4]) = ek;
            uint2 vh;
            vh.x = pack_h2(vv.y, vv.x);
            vh.y = pack_h2(vv.w, vv.z);
            *reinterpret_cast<uint2*>(&sB[row][c4]) = vh;
        }

        // prefetch t+2 into the stage just drained (safe: same thread's rows)
        if (t + 2 < NT) {
            const int scol = s0 + (t + 2) * 64 + c4;
#pragma unroll
            for (int ib = 0; ib < 4; ++ib) {
                const int row = ib * 16 + r0;
                cp_async16(smem_u32(sKf + st * 4096 + row * 64 + c4), kg + (size_t)row * SQ + scol);
                cp_async16(smem_u32(sVf + st * 4096 + row * 64 + c4), vg + (size_t)row * SQ + scol);
            }
        }
        cp_commit();

        __syncthreads();             // the ONE barrier per tile

#pragma unroll
        for (int kk = 0; kk < 4; ++kk) {
            uint32_t a[4];
            ldsm_x4(a, smem_u32(&sA[wi * 16 + (lane & 15)]
                                  [kk * 16 + (lane >> 4) * 8]));
#pragma unroll
            for (int np = 0; np < 2; ++np) {
                uint32_t b[4];
                ldsm_x4(b, smem_u32(&sB[wn * 32 + (np * 2 + (lane >> 4)) * 8 + (lane & 7)]
                                      [kk * 16 + ((lane >> 3) & 1) * 8]));
                mma_f16(acc[np * 2],     a, b);
                mma_f16(acc[np * 2 + 1], a, b + 2);
            }
            if (wn == 1) {
                uint32_t b2[2];
                ldsm_x2(b2, smem_u32(&sB[64 + (lane & 7)]
                                       [kk * 16 + ((lane >> 3) & 1) * 8]));
                mma_f16(accz, a, b2);
            }
        }
    }

    // plain stores of this chunk's partials (no atomics)
    float* ctxp = g_ctx_part + ((size_t)blockIdx.x * NHEADS + head) * DH * DH;
    const int i0 = wi * 16 + (lane >> 2);
    const int jb = wn * 32 + (lane & 3) * 2;
#pragma unroll
    for (int n = 0; n < 4; ++n) {
        const int j = jb + n * 8;
        *reinterpret_cast<float2*>(&ctxp[i0 * 64 + j])       = make_float2(acc[n][0], acc[n][1]);
        *reinterpret_cast<float2*>(&ctxp[(i0 + 8) * 64 + j]) = make_float2(acc[n][2], acc[n][3]);
    }
    if (wn == 1 && (lane & 3) == 0) {
        float* zkp = g_zk_part + ((size_t)blockIdx.x * NHEADS + head) * DH;
        zkp[i0]     = accz[0];
        zkp[i0 + 8] = accz[2];
    }
}

// ---------------------------------------------------------------------------
// Kernel 2: out[j,s] = (1/Zq_s) * sum_i ctxh[i][j] * exp(q[i,s])
// grid (SQ/128/OUT_TPC, NHEADS), block 256. Sums ctx partials in prologue.
// dyn smem: sQf[2][8192]f | sQh[2][64][136]h | sCt[64][72]h | sZp[8][132]f
//           | sCs[2][128]f | sInv[64]f
// ---------------------------------------------------------------------------
#define OUT_SQH_OFF 65536
#define OUT_SCT_OFF 100352
#define OUT_SZP_OFF 109568
#define OUT_SCS_OFF 113792
#define OUT_SINV_OFF 114816
#define OUT_SMEM    115072

__global__ __launch_bounds__(256, 2) void out_kernel(const float* __restrict__ q,
                                                     float* __restrict__ out) {
    extern __shared__ char dyn[];
    float* sQf = reinterpret_cast<float*>(dyn);
    __half (*sQb)[136] = reinterpret_cast<__half(*)[136]>(dyn + OUT_SQH_OFF);
    __half (*sCt)[72]  = reinterpret_cast<__half(*)[72]>(dyn + OUT_SCT_OFF);
    float (*sZp)[132]  = reinterpret_cast<float(*)[132]>(dyn + OUT_SZP_OFF);
    float* sCs  = reinterpret_cast<float*>(dyn + OUT_SCS_OFF);   // [2][128]
    float* sInv = reinterpret_cast<float*>(dyn + OUT_SINV_OFF);

    const int head = blockIdx.y;
    const int tid  = threadIdx.x;
    const int warp = tid >> 5;
    const int lane = tid & 31;

    const float* qg = q + (size_t)head * DH * SQ;
    const int sbase = blockIdx.x * OUT_TPC * 128;

    const int r  = tid >> 5;          // 0..7
    const int c4 = (tid & 31) * 4;    // 0..124

    // stage q tiles 0,1 first: DRAM busy while we sum partials from L2
#pragma unroll
    for (int st = 0; st < 2; ++st) {
        const int scol = sbase + st * 128 + c4;
#pragma unroll
        for (int ib = 0; ib < 8; ++ib) {
            const int d = ib * 8 + r;
            cp_async16(smem_u32(sQf + st * 8192 + d * 128 + c4), qg + (size_t)d * SQ + scol);
        }
        cp_commit();
    }

    // Zk: sum 8 chunk partials -> 0.125/Zk
    if (tid < 64) {
        float z = 0.0f;
#pragma unroll
        for (int c = 0; c < CHUNKS; ++c)
            z += g_zk_part[((size_t)c * NHEADS + head) * DH + tid];
        sInv[tid] = __fdividef(0.125f, z);
    }
    __syncthreads();

    // ctx: sum 8 chunk partials, normalize, pack to half
    {
        const int i  = tid >> 2;          // row
        const int j0 = (tid & 3) * 16;    // 16 cols per thread
        float s[16];
#pragma unroll
        for (int x = 0; x < 16; ++x) s[x] = 0.0f;
#pragma unroll
        for (int c = 0; c < CHUNKS; ++c) {
            const float* p = g_ctx_part + ((size_t)c * NHEADS + head) * DH * DH + i * 64 + j0;
#pragma unroll
            for (int x = 0; x < 4; ++x) {
                float4 f = *reinterpret_cast<const float4*>(p + x * 4);
                s[x * 4]     += f.x;
                s[x * 4 + 1] += f.y;
                s[x * 4 + 2] += f.z;
                s[x * 4 + 3] += f.w;
            }
        }
        const float inv = sInv[i];
        uint4 o0, o1;
        o0.x = pack_h2(s[1] * inv,  s[0] * inv);
        o0.y = pack_h2(s[3] * inv,  s[2] * inv);
        o0.z = pack_h2(s[5] * inv,  s[4] * inv);
        o0.w = pack_h2(s[7] * inv,  s[6] * inv);
        o1.x = pack_h2(s[9] * inv,  s[8] * inv);
        o1.y = pack_h2(s[11] * inv, s[10] * inv);
        o1.z = pack_h2(s[13] * inv, s[12] * inv);
        o1.w = pack_h2(s[15] * inv, s[14] * inv);
        *reinterpret_cast<uint4*>(&sCt[i][j0])     = o0;
        *reinterpret_cast<uint4*>(&sCt[i][j0 + 8]) = o1;
    }

    const int jw = (warp & 3) * 16;
    const int sw = (warp >> 2) * 64;

    for (int t = 0; t < OUT_TPC; ++t) {
        const int st = t & 1;
        __half (*sQ)[136] = sQb + st * 64;

        cp_wait1();

        // convert exp(q) -> half (per-thread self-consistent), Zq partials
        const float* qf = sQf + st * 8192;
        float4 zp = make_float4(0.f, 0.f, 0.f, 0.f);
#pragma unroll
        for (int ib = 0; ib < 8; ++ib) {
            const int d = ib * 8 + r;
            float4 qv = *reinterpret_cast<const float4*>(qf + d * 128 + c4);
            uint2 eq;
            eq.x = ex2_h2(pack_h2(qv.y * LOG2E, qv.x * LOG2E));
            eq.y = ex2_h2(pack_h2(qv.w * LOG2E, qv.z * LOG2E));
            *reinterpret_cast<uint2*>(&sQ[d][c4]) = eq;
            float2 e0 = __half22float2(*reinterpret_cast<__half2*>(&eq.x));
            float2 e1 = __half22float2(*reinterpret_cast<__half2*>(&eq.y));
            zp.x += e0.x; zp.y += e0.y; zp.z += e1.x; zp.w += e1.y;
        }
        *reinterpret_cast<float4*>(&sZp[r][c4]) = zp;

        // prefetch t+2
        if (t + 2 < OUT_TPC) {
            const int scol = sbase + (t + 2) * 128 + c4;
#pragma unroll
            for (int ib = 0; ib < 8; ++ib) {
                const int d = ib * 8 + r;
                cp_async16(smem_u32(sQf + st * 8192 + d * 128 + c4), qg + (size_t)d * SQ + scol);
            }
        }
        cp_commit();

        __syncthreads();             // sQh + sZp ready

        if (tid < 128) {
            float z = 0.0f;
#pragma unroll
            for (int d = 0; d < 8; ++d) z += sZp[d][tid];
            sCs[st * 128 + tid] = __fdividef(1.0f, z);
        }

        float acc[8][4];
#pragma unroll
        for (int n = 0; n < 8; ++n)
#pragma unroll
            for (int c = 0; c < 4; ++c) acc[n][c] = 0.0f;

#pragma unroll
        for (int kk = 0; kk < 4; ++kk) {
            uint32_t a[4];
            ldsm_x4t(a, smem_u32(&sCt[kk * 16 + (lane & 7) + (lane >> 4) * 8]
                                    [jw + ((lane >> 3) & 1) * 8]));
#pragma unroll
            for (int np = 0; np < 4; ++np) {
                uint32_t b[4];
                ldsm_x4t(b, smem_u32(&sQ[kk * 16 + (lane & 7) + ((lane >> 3) & 1) * 8]
                                        [sw + (np * 2 + (lane >> 4)) * 8]));
                mma_f16(acc[np * 2],     a, b);
                mma_f16(acc[np * 2 + 1], a, b + 2);
            }
        }
        __syncthreads();             // sCs ready; sZp consumed

        float* og = out + (size_t)head * DH * SQ + sbase + t * 128;
        const int j0 = jw + (lane >> 2);
        const int sc = (lane & 3) * 2;
#pragma unroll
        for (int n = 0; n < 8; ++n) {
            const int s = sw + n * 8 + sc;
            const float inv0 = sCs[st * 128 + s];
            const float inv1 = sCs[st * 128 + s + 1];
            float2 w0 = make_float2(acc[n][0] * inv0, acc[n][1] * inv1);
            float2 w1 = make_float2(acc[n][2] * inv0, acc[n][3] * inv1);
            *reinterpret_cast<float2*>(og + (size_t)j0 * SQ + s) = w0;
            *reinterpret_cast<float2*>(og + (size_t)(j0 + 8) * SQ + s) = w1;
        }
    }
}

// ---------------------------------------------------------------------------
extern "C" void kernel_launch(void* const* d_in, const int* in_sizes, int n_in,
                              void* d_out, int out_size) {
    const float* q = (const float*)d_in[0];
    const float* k = (const float*)d_in[1];
    const float* v = (const float*)d_in[2];
    float* out = (float*)d_out;

    cudaFuncSetAttribute(ctx_kernel, cudaFuncAttributeMaxDynamicSharedMemorySize, CTX_SMEM);
    cudaFuncSetAttribute(out_kernel, cudaFuncAttributeMaxDynamicSharedMemorySize, OUT_SMEM);

    ctx_kernel<<<dim3(CHUNKS, NHEADS), 256, CTX_SMEM>>>(k, v);
    out_kernel<<<dim3(SQ / 128 / OUT_TPC, NHEADS), 256, OUT_SMEM>>>(q, out);
}

// round 8
// speedup vs baseline: 1.1331x; 1.0730x over previous
#include <cuda_runtime.h>
#include <cuda_fp16.h>
#include <cstdint>

// LinearAttend: q,k,v [4][8][64][8192] f32 -> out same shape.
//   ks = softmax(k, axis=s); qs = softmax(q, axis=d) * D^-0.5
//   ctx = ks @ v^T (64x64/head); out = ctx^T @ qs
// fp16 m16n8k16 MMA (fp32 accum), ldmatrix feed, ex2.approx.f16x2 exps,
// Zk via ones-column MMA, atomic-free split-K partials.
// This round: partial-reduction moved back to a tiny norm kernel; out_kernel
// made lean (31KB smem, <=64 regs, 4 CTAs/SM) for occupancy-driven overlap.

#define SQ 8192
#define DH 64
#define NHEADS 32
#define CHUNKS 8
#define CHUNK_S (SQ / CHUNKS)     // 1024 -> 16 tiles of 64
#define LOG2E 1.4426950408889634f

__device__ float  g_ctx_part[CHUNKS * NHEADS * DH * DH];  // 4 MB partials
__device__ float  g_zk_part[CHUNKS * NHEADS * DH];
__device__ __half g_ctxh[NHEADS * DH * DH];               // normalized ctx

__device__ __forceinline__ uint32_t smem_u32(const void* p) {
    return (uint32_t)__cvta_generic_to_shared(p);
}
__device__ __forceinline__ void cp_async16(uint32_t dst, const void* src) {
    asm volatile("cp.async.cg.shared.global [%0], [%1], 16;" :: "r"(dst), "l"(src));
}
__device__ __forceinline__ void cp_commit() {
    asm volatile("cp.async.commit_group;");
}
__device__ __forceinline__ void cp_wait1() {
    asm volatile("cp.async.wait_group 1;");
}
__device__ __forceinline__ void ldsm_x4(uint32_t* r, uint32_t a) {
    asm volatile("ldmatrix.sync.aligned.m8n8.x4.shared.b16 {%0,%1,%2,%3}, [%4];"
                 : "=r"(r[0]), "=r"(r[1]), "=r"(r[2]), "=r"(r[3]) : "r"(a));
}
__device__ __forceinline__ void ldsm_x2(uint32_t* r, uint32_t a) {
    asm volatile("ldmatrix.sync.aligned.m8n8.x2.shared.b16 {%0,%1}, [%2];"
                 : "=r"(r[0]), "=r"(r[1]) : "r"(a));
}
__device__ __forceinline__ void ldsm_x4t(uint32_t* r, uint32_t a) {
    asm volatile("ldmatrix.sync.aligned.m8n8.x4.trans.shared.b16 {%0,%1,%2,%3}, [%4];"
                 : "=r"(r[0]), "=r"(r[1]), "=r"(r[2]), "=r"(r[3]) : "r"(a));
}
__device__ __forceinline__ void mma_f16(float* d, const uint32_t* a, const uint32_t* b) {
    asm volatile(
        "mma.sync.aligned.m16n8k16.row.col.f32.f16.f16.f32 "
        "{%0,%1,%2,%3}, {%4,%5,%6,%7}, {%8,%9}, {%0,%1,%2,%3};"
        : "+f"(d[0]), "+f"(d[1]), "+f"(d[2]), "+f"(d[3])
        : "r"(a[0]), "r"(a[1]), "r"(a[2]), "r"(a[3]), "r"(b[0]), "r"(b[1]));
}
__device__ __forceinline__ uint32_t pack_h2(float hi, float lo) {
    uint32_t h;
    asm("cvt.rn.f16x2.f32 %0, %1, %2;" : "=r"(h) : "f"(hi), "f"(lo));
    return h;
}
__device__ __forceinline__ uint32_t ex2_h2(uint32_t y) {
    uint32_t r;
    asm("ex2.approx.f16x2 %0, %1;" : "=r"(r) : "r"(y));
    return r;
}

// ---------------------------------------------------------------------------
// Kernel 1: ctx partials. grid (CHUNKS, NHEADS), block 256.
// (unchanged from round 7: 27.7us, cp.async 2-stage, one barrier/tile)
// ---------------------------------------------------------------------------
#define CTX_SVF_OFF 32768
#define CTX_SA_OFF  65536
#define CTX_SB_OFF  83968
#define CTX_SMEM    104704

__global__ __launch_bounds__(256, 2) void ctx_kernel(const float* __restrict__ k,
                                                     const float* __restrict__ v) {
    extern __shared__ char dyn[];
    float* sKf = reinterpret_cast<float*>(dyn);
    float* sVf = reinterpret_cast<float*>(dyn + CTX_SVF_OFF);
    __half (*sAb)[72] = reinterpret_cast<__half(*)[72]>(dyn + CTX_SA_OFF);
    __half (*sBb)[72] = reinterpret_cast<__half(*)[72]>(dyn + CTX_SB_OFF);

    const int head = blockIdx.y;
    const int s0   = blockIdx.x * CHUNK_S;
    const int tid  = threadIdx.x;
    const int warp = tid >> 5;
    const int lane = tid & 31;
    const int wi   = warp & 3;
    const int wn   = warp >> 2;

    const float* kg = k + (size_t)head * DH * SQ;
    const float* vg = v + (size_t)head * DH * SQ;

    for (int e = tid; e < 2 * 8 * 36; e += 256) {
        const int stg = e / (8 * 36);
        const int rem = e % (8 * 36);
        const int row = 64 + rem / 36;
        *reinterpret_cast<uint32_t*>(&sBb[stg * 72 + row][(rem % 36) * 2]) =
            (row == 64) ? 0x3C003C00u : 0u;
    }

    const int r0 = tid >> 4;
    const int c4 = (tid & 15) * 4;

#pragma unroll
    for (int st = 0; st < 2; ++st) {
        const int scol = s0 + st * 64 + c4;
#pragma unroll
        for (int ib = 0; ib < 4; ++ib) {
            const int row = ib * 16 + r0;
            cp_async16(smem_u32(sKf + st * 4096 + row * 64 + c4), kg + (size_t)row * SQ + scol);
            cp_async16(smem_u32(sVf + st * 4096 + row * 64 + c4), vg + (size_t)row * SQ + scol);
        }
        cp_commit();
    }

    float acc[4][4];
#pragma unroll
    for (int n = 0; n < 4; ++n)
#pragma unroll
        for (int c = 0; c < 4; ++c) acc[n][c] = 0.0f;
    float accz[4] = {0.f, 0.f, 0.f, 0.f};

    const int NT = CHUNK_S / 64;
    for (int t = 0; t < NT; ++t) {
        const int st = t & 1;
        __half (*sA)[72] = sAb + st * 64;
        __half (*sB)[72] = sBb + st * 72;

        cp_wait1();

        const float* kf = sKf + st * 4096;
        const float* vf = sVf + st * 4096;
#pragma unroll
        for (int ib = 0; ib < 4; ++ib) {
            const int row = ib * 16 + r0;
            float4 kv = *reinterpret_cast<const float4*>(kf + row * 64 + c4);
            float4 vv = *reinterpret_cast<const float4*>(vf + row * 64 + c4);
            uint2 ek;
            ek.x = ex2_h2(pack_h2(kv.y * LOG2E, kv.x * LOG2E));
            ek.y = ex2_h2(pack_h2(kv.w * LOG2E, kv.z * LOG2E));
            *reinterpret_cast<uint2*>(&sA[row][c4]) = ek;
            uint2 vh;
            vh.x = pack_h2(vv.y, vv.x);
            vh.y = pack_h2(vv.w, vv.z);
            *reinterpret_cast<uint2*>(&sB[row][c4]) = vh;
        }

        if (t + 2 < NT) {
            const int scol = s0 + (t + 2) * 64 + c4;
#pragma unroll
            for (int ib = 0; ib < 4; ++ib) {
                const int row = ib * 16 + r0;
                cp_async16(smem_u32(sKf + st * 4096 + row * 64 + c4), kg + (size_t)row * SQ + scol);
                cp_async16(smem_u32(sVf + st * 4096 + row * 64 + c4), vg + (size_t)row * SQ + scol);
            }
        }
        cp_commit();

        __syncthreads();

#pragma unroll
        for (int kk = 0; kk < 4; ++kk) {
            uint32_t a[4];
            ldsm_x4(a, smem_u32(&sA[wi * 16 + (lane & 15)]
                                  [kk * 16 + (lane >> 4) * 8]));
#pragma unroll
            for (int np = 0; np < 2; ++np) {
                uint32_t b[4];
                ldsm_x4(b, smem_u32(&sB[wn * 32 + (np * 2 + (lane >> 4)) * 8 + (lane & 7)]
                                      [kk * 16 + ((lane >> 3) & 1) * 8]));
                mma_f16(acc[np * 2],     a, b);
                mma_f16(acc[np * 2 + 1], a, b + 2);
            }
            if (wn == 1) {
                uint32_t b2[2];
                ldsm_x2(b2, smem_u32(&sB[64 + (lane & 7)]
                                       [kk * 16 + ((lane >> 3) & 1) * 8]));
                mma_f16(accz, a, b2);
            }
        }
    }

    float* ctxp = g_ctx_part + ((size_t)blockIdx.x * NHEADS + head) * DH * DH;
    const int i0 = wi * 16 + (lane >> 2);
    const int jb = wn * 32 + (lane & 3) * 2;
#pragma unroll
    for (int n = 0; n < 4; ++n) {
        const int j = jb + n * 8;
        *reinterpret_cast<float2*>(&ctxp[i0 * 64 + j])       = make_float2(acc[n][0], acc[n][1]);
        *reinterpret_cast<float2*>(&ctxp[(i0 + 8) * 64 + j]) = make_float2(acc[n][2], acc[n][3]);
    }
    if (wn == 1 && (lane & 3) == 0) {
        float* zkp = g_zk_part + ((size_t)blockIdx.x * NHEADS + head) * DH;
        zkp[i0]     = accz[0];
        zkp[i0 + 8] = accz[2];
    }
}

// ---------------------------------------------------------------------------
// Kernel 1.5: sum partials, normalize: ctxh[i][j] = sum_c part[c]*0.125/Zk[i]
// grid NHEADS, block 256. Thread owns 16 consecutive elems of one row.
// ---------------------------------------------------------------------------
__global__ __launch_bounds__(256) void norm_kernel() {
    const int head = blockIdx.x;
    const int tid  = threadIdx.x;
    const int base = tid * 16;
    const int i    = base >> 6;

    float z = 0.0f;
#pragma unroll
    for (int c = 0; c < CHUNKS; ++c)
        z += g_zk_part[((size_t)c * NHEADS + head) * DH + i];
    const float inv = __fdividef(0.125f, z);

    float s[16];
#pragma unroll
    for (int x = 0; x < 16; ++x) s[x] = 0.0f;
#pragma unroll
    for (int c = 0; c < CHUNKS; ++c) {
        const float* p = g_ctx_part + ((size_t)c * NHEADS + head) * DH * DH + base;
#pragma unroll
        for (int x = 0; x < 4; ++x) {
            float4 f = *reinterpret_cast<const float4*>(p + x * 4);
            s[x * 4]     += f.x;
            s[x * 4 + 1] += f.y;
            s[x * 4 + 2] += f.z;
            s[x * 4 + 3] += f.w;
        }
    }
    uint4 o0, o1;
    o0.x = pack_h2(s[1] * inv,  s[0] * inv);
    o0.y = pack_h2(s[3] * inv,  s[2] * inv);
    o0.z = pack_h2(s[5] * inv,  s[4] * inv);
    o0.w = pack_h2(s[7] * inv,  s[6] * inv);
    o1.x = pack_h2(s[9] * inv,  s[8] * inv);
    o1.y = pack_h2(s[11] * inv, s[10] * inv);
    o1.z = pack_h2(s[13] * inv, s[12] * inv);
    o1.w = pack_h2(s[15] * inv, s[14] * inv);
    __half* och = g_ctxh + head * DH * DH + base;
    *reinterpret_cast<uint4*>(och)     = o0;
    *reinterpret_cast<uint4*>(och + 8) = o1;
}

// ---------------------------------------------------------------------------
// Kernel 2: out[j,s] = (1/Zq_s) * sum_i ctxh[i][j] * exp(q[i,s])
// grid (SQ/128, NHEADS), block 256, one 64x128 tile per CTA. Lean: ~31KB
// smem, <=64 regs (launch_bounds 4 blocks/SM), q in two 4xfloat4 batches.
// ---------------------------------------------------------------------------
__global__ __launch_bounds__(256, 4) void out_kernel(const float* __restrict__ q,
                                                     float* __restrict__ out) {
    __shared__ __half sCt[64][72];    // [i][j] normalized half context
    __shared__ __half sQ[64][136];    // [i][s] exp(q) half
    __shared__ float  sZp[8][132];    // Zq partials
    __shared__ float  sCs[128];       // 1/Zq_s

    const int head = blockIdx.y;
    const int s0   = blockIdx.x * 128;
    const int tid  = threadIdx.x;
    const int warp = tid >> 5;
    const int lane = tid & 31;

    const float* qg = q + (size_t)head * DH * SQ + s0;
    const int r  = tid >> 5;          // 0..7
    const int c4 = (tid & 31) * 4;    // 0..124

    // context tile: 256 threads x 2 uint4 = 8 KB (hits L2)
    {
        const uint4* src = reinterpret_cast<const uint4*>(g_ctxh + head * DH * DH);
        uint4 c0 = src[tid * 2];
        uint4 c1 = src[tid * 2 + 1];
        const int i = tid >> 2;
        const int j = (tid & 3) * 16;
        *reinterpret_cast<uint4*>(&sCt[i][j])     = c0;
        *reinterpret_cast<uint4*>(&sCt[i][j + 8]) = c1;
    }

    // q: two batches of 4 float4 (halves register pressure)
    float4 zp = make_float4(0.f, 0.f, 0.f, 0.f);
#pragma unroll
    for (int half = 0; half < 2; ++half) {
        float4 qv[4];
#pragma unroll
        for (int ib = 0; ib < 4; ++ib) {
            const int d = (half * 4 + ib) * 8 + r;
            qv[ib] = *reinterpret_cast<const float4*>(qg + (size_t)d * SQ + c4);
        }
#pragma unroll
        for (int ib = 0; ib < 4; ++ib) {
            const int d = (half * 4 + ib) * 8 + r;
            uint2 eq;
            eq.x = ex2_h2(pack_h2(qv[ib].y * LOG2E, qv[ib].x * LOG2E));
            eq.y = ex2_h2(pack_h2(qv[ib].w * LOG2E, qv[ib].z * LOG2E));
            *reinterpret_cast<uint2*>(&sQ[d][c4]) = eq;
            float2 e0 = __half22float2(*reinterpret_cast<__half2*>(&eq.x));
            float2 e1 = __half22float2(*reinterpret_cast<__half2*>(&eq.y));
            zp.x += e0.x; zp.y += e0.y; zp.z += e1.x; zp.w += e1.y;
        }
    }
    *reinterpret_cast<float4*>(&sZp[r][c4]) = zp;
    __syncthreads();

    if (tid < 128) {
        float z = 0.0f;
#pragma unroll
        for (int d = 0; d < 8; ++d) z += sZp[d][tid];
        sCs[tid] = __fdividef(1.0f, z);
    }

    float acc[8][4];
#pragma unroll
    for (int n = 0; n < 8; ++n)
#pragma unroll
        for (int c = 0; c < 4; ++c) acc[n][c] = 0.0f;

    const int jw = (warp & 3) * 16;   // j offset
    const int sw = (warp >> 2) * 64;  // s offset

#pragma unroll
    for (int kk = 0; kk < 4; ++kk) {
        uint32_t a[4];
        ldsm_x4t(a, smem_u32(&sCt[kk * 16 + (lane & 7) + (lane >> 4) * 8]
                                [jw + ((lane >> 3) & 1) * 8]));
#pragma unroll
        for (int np = 0; np < 4; ++np) {
            uint32_t b[4];
            ldsm_x4t(b, smem_u32(&sQ[kk * 16 + (lane & 7) + ((lane >> 3) & 1) * 8]
                                    [sw + (np * 2 + (lane >> 4)) * 8]));
            mma_f16(acc[np * 2],     a, b);
            mma_f16(acc[np * 2 + 1], a, b + 2);
        }
    }
    __syncthreads();   // sCs ready (reduce overlapped with MMA issue)

    float* og = out + (size_t)head * DH * SQ + s0;
    const int j0 = jw + (lane >> 2);
    const int sc = (lane & 3) * 2;
#pragma unroll
    for (int n = 0; n < 8; ++n) {
        const int s = sw + n * 8 + sc;
        const float inv0 = sCs[s];
        const float inv1 = sCs[s + 1];
        float2 w0 = make_float2(acc[n][0] * inv0, acc[n][1] * inv1);
        float2 w1 = make_float2(acc[n][2] * inv0, acc[n][3] * inv1);
        *reinterpret_cast<float2*>(og + (size_t)j0 * SQ + s) = w0;
        *reinterpret_cast<float2*>(og + (size_t)(j0 + 8) * SQ + s) = w1;
    }
}

// ---------------------------------------------------------------------------
extern "C" void kernel_launch(void* const* d_in, const int* in_sizes, int n_in,
                              void* d_out, int out_size) {
    const float* q = (const float*)d_in[0];
    const float* k = (const float*)d_in[1];
    const float* v = (const float*)d_in[2];
    float* out = (float*)d_out;

    cudaFuncSetAttribute(ctx_kernel, cudaFuncAttributeMaxDynamicSharedMemorySize, CTX_SMEM);

    ctx_kernel<<<dim3(CHUNKS, NHEADS), 256, CTX_SMEM>>>(k, v);
    norm_kernel<<<NHEADS, 256>>>();
    out_kernel<<<dim3(SQ / 128, NHEADS), 256>>>(q, out);
}